// round 4
// baseline (speedup 1.0000x reference)
#include <cuda_runtime.h>
#include <cstdint>

// Problem constants
#define LSEQ   128
#define BATCH  32
#define DIM    64
#define HID    32
#define NROWS  4096          // LSEQ*BATCH
#define NSTEPS 10
#define NELEMS 262144        // NROWS*DIM

// ---------------- device scratch (no allocation allowed) ----------------
__device__ float g_S[LSEQ * DIM * HID];     // suffix sums of W1: [t][d][h]
__device__ float g_pre1[NROWS * HID];       // base hidden pre-activation (+b1)
__device__ float g_acc[NROWS * DIM];        // accumulated dx per row
__device__ float g_score[NROWS * DIM];
__device__ float g_rowsq[NROWS];
__device__ float g_abspart[256];
__device__ float g_snorm;
__device__ float g_steploss;
__device__ unsigned int g_ctr[32];

// ---------------- threefry2x32 (JAX default PRNG) ----------------
#define TF_ROT(x, r) (((x) << (r)) | ((x) >> (32 - (r))))
__host__ __device__ inline void tf2x32(unsigned k0, unsigned k1,
                                       unsigned x0, unsigned x1,
                                       unsigned* o0, unsigned* o1) {
  unsigned ks0 = k0, ks1 = k1, ks2 = k0 ^ k1 ^ 0x1BD11BDAu;
  x0 += ks0; x1 += ks1;
#define TF_R4(a,b,c,d) \
  x0 += x1; x1 = TF_ROT(x1,a); x1 ^= x0; \
  x0 += x1; x1 = TF_ROT(x1,b); x1 ^= x0; \
  x0 += x1; x1 = TF_ROT(x1,c); x1 ^= x0; \
  x0 += x1; x1 = TF_ROT(x1,d); x1 ^= x0;
  TF_R4(13,15,26,6)  x0 += ks1; x1 += ks2 + 1u;
  TF_R4(17,29,16,24) x0 += ks2; x1 += ks0 + 2u;
  TF_R4(13,15,26,6)  x0 += ks0; x1 += ks1 + 3u;
  TF_R4(17,29,16,24) x0 += ks1; x1 += ks2 + 4u;
  TF_R4(13,15,26,6)  x0 += ks2; x1 += ks0 + 5u;
#undef TF_R4
  *o0 = x0; *o1 = x1;
}

// bits -> uniform in [lo, 1) -> sqrt(2)*erfinv (XLA/Giles f32 polynomial)
__device__ __forceinline__ float bits_to_normal(unsigned bits) {
  float f = __uint_as_float((bits >> 9) | 0x3f800000u) - 1.0f;   // [0,1)
  const float lo = __uint_as_float(0xBF7FFFFFu);                 // nextafter(-1,0)
  float u = fmaxf(lo, f * 2.0f + lo);                            // (hi-lo)==2.0f in f32
  float w = -log1pf(-u * u);
  float p;
  if (w < 5.0f) {
    w -= 2.5f;
    p = 2.81022636e-08f;
    p = fmaf(p, w, 3.43273939e-07f);
    p = fmaf(p, w, -3.5233877e-06f);
    p = fmaf(p, w, -4.39150654e-06f);
    p = fmaf(p, w, 0.00021858087f);
    p = fmaf(p, w, -0.00125372503f);
    p = fmaf(p, w, -0.00417768164f);
    p = fmaf(p, w, 0.246640727f);
    p = fmaf(p, w, 1.50140941f);
  } else {
    w = sqrtf(w) - 3.0f;
    p = -0.000200214257f;
    p = fmaf(p, w, 0.000100950558f);
    p = fmaf(p, w, 0.00134934322f);
    p = fmaf(p, w, -0.00367342844f);
    p = fmaf(p, w, 0.00573950773f);
    p = fmaf(p, w, -0.0076224613f);
    p = fmaf(p, w, 0.00943887047f);
    p = fmaf(p, w, 1.00167406f);
    p = fmaf(p, w, 2.83297682f);
  }
  return 1.41421356237f * (p * u);
}

// ---------------- kernels ----------------
__global__ __launch_bounds__(256) void kInit() {
  int idx = blockIdx.x * 256 + threadIdx.x;
#pragma unroll
  for (int i = 0; i < 4; ++i) g_acc[idx * 4 + i] = 0.0f;
  if (blockIdx.x == 0) {
    if (threadIdx.x < 32) g_ctr[threadIdx.x] = 0u;
    if (threadIdx.x == 0) g_steploss = 0.0f;
  }
}

// suffix sums over t of W1 reshaped (128, 64*32): S[t][q] = sum_{tt>t} W1[tt*2048+q]
__global__ __launch_bounds__(256) void kSuffix(const float* __restrict__ W1) {
  int q = blockIdx.x * 256 + threadIdx.x;   // 2048 threads
  float s = 0.0f;
  g_S[127 * 2048 + q] = 0.0f;
  for (int t = 126; t >= 0; --t) {
    s += W1[(t + 1) * 2048 + q];
    g_S[t * 2048 + q] = s;
  }
}

// pre1[n=j*32+b][h] = b1[h] + sum_d emb[b,j,d] * S[j][d][h]
__global__ __launch_bounds__(256) void kH0(const float* __restrict__ emb,
                                           const float* __restrict__ b1) {
  __shared__ float sEmb[2048];  // [b][d]
  __shared__ float sS[2048];    // [d][h]
  int j = blockIdx.x;
  int tid = threadIdx.x;
  for (int i = tid; i < 2048; i += 256) {
    int b = i >> 6, d = i & 63;
    sEmb[i] = emb[b * 8192 + j * 64 + d];
    sS[i] = g_S[j * 2048 + i];
  }
  __syncthreads();
  for (int o = tid; o < 1024; o += 256) {
    int b = o >> 5, h = o & 31;
    float acc = b1[h];
#pragma unroll 8
    for (int d = 0; d < 64; ++d) acc = fmaf(sEmb[b * 64 + d], sS[d * 32 + h], acc);
    g_pre1[(j * 32 + b) * 32 + h] = acc;
  }
}

// score for all 4096 rows + tail reduction to g_snorm.
// Block t handles the 32 rows with n mod 128 == t (they share the W1 tile).
__global__ __launch_bounds__(256) void kScore(const float* __restrict__ W1,
                                              const float* __restrict__ W2,
                                              const float* __restrict__ b2,
                                              float tval, int s) {
  __shared__ float sW[2048];    // W1 block for this t: [d][h]
  __shared__ float sW2[2048];   // [h][d]
  __shared__ float sb2[64];
  __shared__ float swt[32];
  int t = blockIdx.x;
  int tid = threadIdx.x;
  int lane = tid & 31, w = tid >> 5;
  for (int i = tid; i < 2048; i += 256) {
    sW[i] = W1[t * 2048 + i];
    sW2[i] = W2[i];
  }
  if (tid < 64) sb2[tid] = b2[tid];
  if (tid < 32) swt[tid] = W1[262144 + tid];
  __syncthreads();

#pragma unroll
  for (int r = 0; r < 4; ++r) {
    int m = w * 4 + r;
    int n = t + 128 * m;
    float a0 = g_acc[n * 64 + lane];
    float a1 = g_acc[n * 64 + 32 + lane];
    float h = g_pre1[n * 32 + lane] + tval * swt[lane];
#pragma unroll
    for (int d = 0; d < 32; ++d)
      h = fmaf(__shfl_sync(0xffffffffu, a0, d), sW[d * 32 + lane], h);
#pragma unroll
    for (int d = 0; d < 32; ++d)
      h = fmaf(__shfl_sync(0xffffffffu, a1, d), sW[(32 + d) * 32 + lane], h);
    h = fmaxf(h, 0.0f);
    float s0 = sb2[lane], s1 = sb2[32 + lane];
#pragma unroll
    for (int hh = 0; hh < 32; ++hh) {
      float hv = __shfl_sync(0xffffffffu, h, hh);
      s0 = fmaf(hv, sW2[hh * 64 + lane], s0);
      s1 = fmaf(hv, sW2[hh * 64 + 32 + lane], s1);
    }
    g_score[n * 64 + lane] = s0;
    g_score[n * 64 + 32 + lane] = s1;
    float rs = fmaf(s0, s0, s1 * s1);
#pragma unroll
    for (int off = 16; off; off >>= 1) rs += __shfl_xor_sync(0xffffffffu, rs, off);
    if (lane == 0) g_rowsq[n] = rs;
  }

  // last-block tail: deterministic reduce of g_rowsq -> snorm
  __shared__ bool sLast;
  __threadfence();
  __syncthreads();
  if (tid == 0) sLast = (atomicAdd(&g_ctr[s], 1u) == gridDim.x - 1);
  __syncthreads();
  if (!sLast) return;
  float v = 0.0f;
  for (int i = 0; i < 16; ++i) v += g_rowsq[tid * 16 + i];
  __shared__ float red[256];
  red[tid] = v;
  __syncthreads();
  for (int off = 128; off; off >>= 1) { if (tid < off) red[tid] += red[tid + off]; __syncthreads(); }
  if (tid == 0) g_snorm = sqrtf(red[0]);
}

// threefry (partitionable mode: bits[e] = o0^o1 of counter (0, e)) + dx + acc update;
// last block computes this step's error contribution
__global__ __launch_bounds__(256) void kUpdate(unsigned k0, unsigned k1, int s) {
  int idx = blockIdx.x * 256 + threadIdx.x;   // 0..131071
  int e0 = idx * 2, e1 = e0 + 1;
  unsigned a0, a1, c0, c1;
  tf2x32(k0, k1, 0u, (unsigned)e0, &a0, &a1);
  tf2x32(k0, k1, 0u, (unsigned)e1, &c0, &c1);
  const float sdt = sqrtf(0.1f);
  float snorm = g_snorm;
  float dW0 = bits_to_normal(a0 ^ a1) * sdt;
  float dW1 = bits_to_normal(c0 ^ c1) * sdt;
  g_acc[e0] += 0.5f * g_score[e0] * 0.1f + snorm * dW0;
  g_acc[e1] += 0.5f * g_score[e1] * 0.1f + snorm * dW1;

  __shared__ bool sLast;
  __threadfence();
  __syncthreads();
  if (threadIdx.x == 0) sLast = (atomicAdd(&g_ctr[10 + s], 1u) == gridDim.x - 1);
  __syncthreads();
  if (!sLast) return;

  // step error: preds reshape splits (L, L*B, D) -> n = i*32+b at t=i;
  // nonzero only when (i*32+b) mod 128 == i -> i_b = 32*(b&3)+b (32 pairs)
  __shared__ float sErr[32];
  int lane = threadIdx.x & 31, w = threadIdx.x >> 5;
#pragma unroll
  for (int r = 0; r < 4; ++r) {
    int b = w + 8 * r;
    int ib = 32 * (b & 3) + b;
    int nb = ib * 32 + b;
    float v0 = g_acc[nb * 64 + lane];
    float v1 = g_acc[nb * 64 + 32 + lane];
    float sq = fmaf(v0, v0, v1 * v1);
#pragma unroll
    for (int off = 16; off; off >>= 1) sq += __shfl_xor_sync(0xffffffffu, sq, off);
    if (lane == 0) sErr[b] = sq;
  }
  __syncthreads();
  if (threadIdx.x == 0) {
    float tot = 0.0f;
    for (int b = 0; b < 32; ++b) tot += sErr[b];
    g_steploss += tot * (1.0f / 64.0f);
  }
}

// Final output:
// xt_fin has shape (L*B, L, D); reshape(L,L,B,D)[i,i,c,d] = xt_fin[32i+(i>>2), 32*(i%4)+c, d]
// out[b,i,d] = (i < 32*(i%4)+b ? emb[i>>2, i, d] : 0) + (i>>2 == b ? acc[32i+b, d] : 0)
// sequence_loss = mean |emb[b,i,d] - out[b,i,d]|
__global__ __launch_bounds__(256) void kFinal(const float* __restrict__ emb,
                                              float* __restrict__ out) {
  int tid = threadIdx.x;
  int base = blockIdx.x * 1024 + tid * 4;     // element index; 4 consecutive d
  int b = base >> 13;
  int i = (base >> 6) & 127;
  int j = i >> 2;
  bool has_emb = i < 32 * (i & 3) + b;
  bool has_acc = (j == b);
  float loc = 0.0f;
#pragma unroll
  for (int q = 0; q < 4; ++q) {
    int d = (base & 63) + q;
    float v = 0.0f;
    if (has_emb) v = emb[j * 8192 + i * 64 + d];
    if (has_acc) v += g_acc[(32 * i + b) * 64 + d];
    out[base + q] = v;
    loc += fabsf(emb[base + q] - v);
  }
  __shared__ float red[256];
  red[tid] = loc;
  __syncthreads();
  for (int off = 128; off; off >>= 1) { if (tid < off) red[tid] += red[tid + off]; __syncthreads(); }
  if (tid == 0) g_abspart[blockIdx.x] = red[0];

  __shared__ bool sLast;
  __threadfence();
  __syncthreads();
  if (tid == 0) sLast = (atomicAdd(&g_ctr[20], 1u) == gridDim.x - 1);
  __syncthreads();
  if (!sLast) return;

  if (tid == 0) {
    double tot = 0.0;
    for (int k = 0; k < 256; ++k) tot += (double)g_abspart[k];
    out[NELEMS] = g_steploss;                       // step_loss
    out[NELEMS + 1] = (float)(tot / 262144.0);      // sequence_loss
  }
}

// ---------------- launch ----------------
extern "C" void kernel_launch(void* const* d_in, const int* in_sizes, int n_in,
                              void* d_out, int out_size) {
  const float* emb = (const float*)d_in[0];
  const float* W1  = (const float*)d_in[1];
  const float* b1  = (const float*)d_in[2];
  const float* W2  = (const float*)d_in[3];
  const float* b2  = (const float*)d_in[4];
  float* out = (float*)d_out;

  // keys = jax.random.split(jax.random.key(42), 10), partitionable mode:
  // keys[i] = threefry2x32(key=(0,42), counter=(0, i)) -> (o0, o1)
  unsigned K0[10], K1[10];
  for (int i = 0; i < 10; ++i) tf2x32(0u, 42u, 0u, (unsigned)i, &K0[i], &K1[i]);

  kInit<<<256, 256>>>();
  kSuffix<<<8, 256>>>(W1);
  kH0<<<128, 256>>>(emb, b1);
  for (int s = 0; s < NSTEPS; ++s) {
    float tval = (float)s * 0.1f;
    kScore<<<128, 256>>>(W1, W2, b2, tval, s);
    kUpdate<<<512, 256>>>(K0[s], K1[s], s);
  }
  kFinal<<<256, 256>>>(emb, out);
}

// round 5
// speedup vs baseline: 1.5250x; 1.5250x over previous
#include <cuda_runtime.h>
#include <cstdint>

#define LSEQ   128
#define NSTEPS 10
#define NB     256     // grid blocks (must all be co-resident)
#define NT     256
#define NBAR   14
#define NELEMS 262144

// ---------------- device scratch ----------------
__device__ float g_C[16 * 2048];        // chunk sums of W1 (8 rows each)
__device__ float g_pre1[4096 * 32];     // base hidden pre-activation (+b1)
__device__ float g_part[NSTEPS * NB];   // per-block rowsq partials, per step
__device__ float g_accout[128 * 64];    // final-gather acc rows (i = 0..127)
__device__ float g_err32[32];           // per-b steploss accumulations
__device__ float g_abspart[NB];
__device__ unsigned g_bar[NBAR];        // zero-init; self-resetting

struct Keys { unsigned k0[NSTEPS]; unsigned k1[NSTEPS]; };

// ---------------- threefry2x32 ----------------
#define TF_ROT(x, r) (((x) << (r)) | ((x) >> (32 - (r))))
__host__ __device__ __forceinline__ void tf2x32(unsigned k0, unsigned k1,
                                                unsigned x0, unsigned x1,
                                                unsigned* o0, unsigned* o1) {
  unsigned ks0 = k0, ks1 = k1, ks2 = k0 ^ k1 ^ 0x1BD11BDAu;
  x0 += ks0; x1 += ks1;
#define TF_R4(a,b,c,d) \
  x0 += x1; x1 = TF_ROT(x1,a); x1 ^= x0; \
  x0 += x1; x1 = TF_ROT(x1,b); x1 ^= x0; \
  x0 += x1; x1 = TF_ROT(x1,c); x1 ^= x0; \
  x0 += x1; x1 = TF_ROT(x1,d); x1 ^= x0;
  TF_R4(13,15,26,6)  x0 += ks1; x1 += ks2 + 1u;
  TF_R4(17,29,16,24) x0 += ks2; x1 += ks0 + 2u;
  TF_R4(13,15,26,6)  x0 += ks0; x1 += ks1 + 3u;
  TF_R4(17,29,16,24) x0 += ks1; x1 += ks2 + 4u;
  TF_R4(13,15,26,6)  x0 += ks2; x1 += ks0 + 5u;
#undef TF_R4
  *o0 = x0; *o1 = x1;
}

__device__ __forceinline__ unsigned tfxor(unsigned k0, unsigned k1, unsigned e) {
  unsigned o0, o1;
  tf2x32(k0, k1, 0u, e, &o0, &o1);
  return o0 ^ o1;
}

// bits -> uniform -> sqrt(2)*erfinv (XLA/Giles f32 polynomial)
__device__ __forceinline__ float bits_to_normal(unsigned bits) {
  float f = __uint_as_float((bits >> 9) | 0x3f800000u) - 1.0f;
  const float lo = __uint_as_float(0xBF7FFFFFu);
  float u = fmaxf(lo, f * 2.0f + lo);
  float w = -log1pf(-u * u);
  float p;
  if (w < 5.0f) {
    w -= 2.5f;
    p = 2.81022636e-08f;
    p = fmaf(p, w, 3.43273939e-07f);
    p = fmaf(p, w, -3.5233877e-06f);
    p = fmaf(p, w, -4.39150654e-06f);
    p = fmaf(p, w, 0.00021858087f);
    p = fmaf(p, w, -0.00125372503f);
    p = fmaf(p, w, -0.00417768164f);
    p = fmaf(p, w, 0.246640727f);
    p = fmaf(p, w, 1.50140941f);
  } else {
    w = sqrtf(w) - 3.0f;
    p = -0.000200214257f;
    p = fmaf(p, w, 0.000100950558f);
    p = fmaf(p, w, 0.00134934322f);
    p = fmaf(p, w, -0.00367342844f);
    p = fmaf(p, w, 0.00573950773f);
    p = fmaf(p, w, -0.0076224613f);
    p = fmaf(p, w, 0.00943887047f);
    p = fmaf(p, w, 1.00167406f);
    p = fmaf(p, w, 2.83297682f);
  }
  return 1.41421356237f * (p * u);
}

__device__ __forceinline__ float wred(float v) {
#pragma unroll
  for (int o = 16; o; o >>= 1) v += __shfl_xor_sync(0xffffffffu, v, o);
  return v;
}

// grid barrier with self-reset: after passing barrier k, block 0 zeroes
// slot (k+12) mod 14 (proved safe: that slot is fully drained, or is a
// future slot whose first use is ordered after this reset via the chain
// of intervening barriers). Leaves all slots zero at kernel exit.
__device__ __forceinline__ void gridbar(int k) {
  __threadfence();
  __syncthreads();
  if (threadIdx.x == 0) {
    atomicAdd(&g_bar[k], 1u);
    while (*(volatile unsigned*)&g_bar[k] < NB) { }
    if (blockIdx.x == 0) {
      atomicExch(&g_bar[(k + NBAR - 2) % NBAR], 0u);
      __threadfence();
    }
  }
  __syncthreads();
}

// ---------------- the one fused kernel ----------------
__global__ void __launch_bounds__(NT, 2) kFused(
    const float* __restrict__ emb, const float* __restrict__ W1,
    const float* __restrict__ b1,  const float* __restrict__ W2,
    const float* __restrict__ b2,  float* __restrict__ out, Keys K) {
  __shared__ float sW[2048];   // W1 tile [d][h] for t
  __shared__ float sW2[2048];  // [h][d]
  __shared__ float sS[2048];   // prologue suffix sums (P1 only)
  __shared__ float sRed[256];
  __shared__ float sb2s[64];
  __shared__ float swts[32];

  const int p = blockIdx.x;
  const int tid = threadIdx.x;
  const int lane = tid & 31, w = tid >> 5;
  const int t = p & 127, half = p >> 7;

  // tile loads (independent of barriers)
  for (int i = tid; i < 2048; i += NT) {
    sW[i]  = W1[t * 2048 + i];
    sW2[i] = W2[i];
  }
  if (tid < 64) sb2s[tid] = b2[tid];
  if (tid < 32) swts[tid] = W1[262144 + tid];

  // ---- P0: chunk sums C[c][q] = sum of W1 rows 8c..8c+7 ----
  if (p < 16) {
    for (int qq = tid; qq < 2048; qq += NT) {
      float s = 0.0f;
#pragma unroll
      for (int r = 0; r < 8; ++r) s += W1[(p * 8 + r) * 2048 + qq];
      __stcg(&g_C[p * 2048 + qq], s);
    }
  }
  gridbar(0);

  // ---- P1: S[j] suffix sums + pre1 rows for j = p ----
  if (p < 128) {
    const int j = p, cj = j >> 3;
    for (int qq = tid; qq < 2048; qq += NT) {
      float s = 0.0f;
      for (int c = cj + 1; c < 16; ++c) s += __ldcg(&g_C[c * 2048 + qq]);
      for (int tt = j + 1; tt < cj * 8 + 8; ++tt) s += W1[tt * 2048 + qq];
      sS[qq] = s;
    }
    __syncthreads();
    const int o = tid * 4;
    const int b = o >> 5, hh = o & 31;
    float v0 = b1[hh], v1 = b1[hh + 1], v2 = b1[hh + 2], v3 = b1[hh + 3];
    const float* er = emb + b * 8192 + j * 64;
#pragma unroll 8
    for (int d = 0; d < 64; ++d) {
      float ev = er[d];
      const float* sp = &sS[d * 32 + hh];
      v0 = fmaf(ev, sp[0], v0); v1 = fmaf(ev, sp[1], v1);
      v2 = fmaf(ev, sp[2], v2); v3 = fmaf(ev, sp[3], v3);
    }
    float* pp = &g_pre1[(j * 32 + b) * 32 + hh];
    pp[0] = v0; pp[1] = v1; pp[2] = v2; pp[3] = v3;
  }
  gridbar(1);

  // ---- per-warp row ownership: rows n0, n1 (mm = 16*half + 2w, +1) ----
  const int mm0 = half * 16 + 2 * w;
  const int n0 = t + 128 * mm0;
  const int n1 = n0 + 128;
  float pre0 = __ldcg(&g_pre1[n0 * 32 + lane]);
  float pre1r = __ldcg(&g_pre1[n1 * 32 + lane]);
  float a00 = 0.f, a01 = 0.f, a10 = 0.f, a11 = 0.f;
  // steploss-special rows: n == 1024*(b&3) + 33*b, b = n&31
  const int b0 = n0 & 31, b1i = n1 & 31;
  const bool sp0 = (n0 == 1024 * (b0 & 3) + 33 * b0);
  const bool sp1 = (n1 == 1024 * (b1i & 3) + 33 * b1i);
  // final-gather rows: (n&31) == (n>>7)
  const bool f0 = ((n0 & 31) == (n0 >> 7));
  const bool f1 = ((n1 & 31) == (n1 >> 7));
  float err0 = 0.f, err1 = 0.f;
  const float sdt = 0.316227766016838f;   // sqrtf(0.1f)

  for (int s = 0; s < NSTEPS; ++s) {
    const float tval = (float)s * 0.1f;
    // hidden h = relu(pre + t*wt + acc . W1tile)
    float h0 = pre0 + tval * swts[lane];
    float h1 = pre1r + tval * swts[lane];
#pragma unroll
    for (int d = 0; d < 32; ++d) {
      float wv = sW[d * 32 + lane];
      h0 = fmaf(__shfl_sync(0xffffffffu, a00, d), wv, h0);
      h1 = fmaf(__shfl_sync(0xffffffffu, a10, d), wv, h1);
    }
#pragma unroll
    for (int d = 0; d < 32; ++d) {
      float wv = sW[(32 + d) * 32 + lane];
      h0 = fmaf(__shfl_sync(0xffffffffu, a01, d), wv, h0);
      h1 = fmaf(__shfl_sync(0xffffffffu, a11, d), wv, h1);
    }
    h0 = fmaxf(h0, 0.0f);
    h1 = fmaxf(h1, 0.0f);
    // score = h @ W2 + b2
    float s00 = sb2s[lane], s01 = sb2s[32 + lane];
    float s10 = sb2s[lane], s11 = sb2s[32 + lane];
#pragma unroll
    for (int hh = 0; hh < 32; ++hh) {
      float w0 = sW2[hh * 64 + lane], w1 = sW2[hh * 64 + 32 + lane];
      float hv0 = __shfl_sync(0xffffffffu, h0, hh);
      float hv1 = __shfl_sync(0xffffffffu, h1, hh);
      s00 = fmaf(hv0, w0, s00); s01 = fmaf(hv0, w1, s01);
      s10 = fmaf(hv1, w0, s10); s11 = fmaf(hv1, w1, s11);
    }
    // block rowsq partial
    float rq = wred(s00 * s00 + s01 * s01 + s10 * s10 + s11 * s11);
    if (lane == 0) sRed[w] = rq;
    __syncthreads();
    if (tid == 0) {
      float bp = 0.f;
#pragma unroll
      for (int i = 0; i < 8; ++i) bp += sRed[i];
      __stcg(&g_part[s * NB + p], bp);
    }
    gridbar(2 + s);
    // deterministic identical snorm in every block
    sRed[tid] = __ldcg(&g_part[s * NB + tid]);
    __syncthreads();
    for (int off = 128; off; off >>= 1) {
      if (tid < off) sRed[tid] += sRed[tid + off];
      __syncthreads();
    }
    const float snorm = sqrtf(sRed[0]);
    // update acc with threefry noise (partitionable: bits[e] = o0^o1 @ (0,e))
    const unsigned k0 = K.k0[s], k1 = K.k1[s];
    {
      float dW;
      dW = bits_to_normal(tfxor(k0, k1, (unsigned)(n0 * 64 + lane))) * sdt;
      a00 += 0.5f * s00 * 0.1f + snorm * dW;
      dW = bits_to_normal(tfxor(k0, k1, (unsigned)(n0 * 64 + 32 + lane))) * sdt;
      a01 += 0.5f * s01 * 0.1f + snorm * dW;
      dW = bits_to_normal(tfxor(k0, k1, (unsigned)(n1 * 64 + lane))) * sdt;
      a10 += 0.5f * s10 * 0.1f + snorm * dW;
      dW = bits_to_normal(tfxor(k0, k1, (unsigned)(n1 * 64 + 32 + lane))) * sdt;
      a11 += 0.5f * s11 * 0.1f + snorm * dW;
    }
    // steploss contributions (owner warps)
    if (sp0) {
      float sq = wred(fmaf(a00, a00, a01 * a01));
      if (lane == 0) err0 += sq * (1.0f / 64.0f);
    }
    if (sp1) {
      float sq = wred(fmaf(a10, a10, a11 * a11));
      if (lane == 0) err1 += sq * (1.0f / 64.0f);
    }
  }

  // publish per-b step errors and final-gather acc rows
  if (sp0 && lane == 0) __stcg(&g_err32[b0], err0);
  if (sp1 && lane == 0) __stcg(&g_err32[b1i], err1);
  if (f0) {
    __stcg(&g_accout[(n0 >> 5) * 64 + lane], a00);
    __stcg(&g_accout[(n0 >> 5) * 64 + 32 + lane], a01);
  }
  if (f1) {
    __stcg(&g_accout[(n1 >> 5) * 64 + lane], a10);
    __stcg(&g_accout[(n1 >> 5) * 64 + 32 + lane], a11);
  }
  gridbar(12);

  // ---- finale sweep: out[b,i,d] + |emb - out| partials ----
  {
    const int base = p * 1024 + tid * 4;
    const int bb = base >> 13;
    const int ii = (base >> 6) & 127;
    const int jj = ii >> 2;
    const bool he = ii < 32 * (ii & 3) + bb;
    const bool ha = (jj == bb);
    float loc = 0.0f;
#pragma unroll
    for (int q = 0; q < 4; ++q) {
      const int d = (base & 63) + q;
      float v = 0.0f;
      if (he) v = emb[jj * 8192 + ii * 64 + d];
      if (ha) v += __ldcg(&g_accout[ii * 64 + d]);
      out[base + q] = v;
      loc += fabsf(emb[base + q] - v);
    }
    sRed[tid] = loc;
    __syncthreads();
    for (int off = 128; off; off >>= 1) {
      if (tid < off) sRed[tid] += sRed[tid + off];
      __syncthreads();
    }
    if (tid == 0) __stcg(&g_abspart[p], sRed[0]);
  }
  gridbar(13);

  if (p == 0 && tid == 0) {
    double tot = 0.0;
    for (int k = 0; k < NB; ++k) tot += (double)__ldcg(&g_abspart[k]);
    float sl = 0.0f;
    for (int b = 0; b < 32; ++b) sl += __ldcg(&g_err32[b]);
    out[NELEMS] = sl;                        // step_loss
    out[NELEMS + 1] = (float)(tot / 262144.0);  // sequence_loss
  }
}

// ---------------- launch ----------------
extern "C" void kernel_launch(void* const* d_in, const int* in_sizes, int n_in,
                              void* d_out, int out_size) {
  const float* emb = (const float*)d_in[0];
  const float* W1  = (const float*)d_in[1];
  const float* b1  = (const float*)d_in[2];
  const float* W2  = (const float*)d_in[3];
  const float* b2  = (const float*)d_in[4];
  float* out = (float*)d_out;

  // keys = jax.random.split(jax.random.key(42), 10) (partitionable):
  // keys[i] = threefry2x32(key=(0,42), counter=(0,i))
  Keys K;
  for (int i = 0; i < NSTEPS; ++i)
    tf2x32(0u, 42u, 0u, (unsigned)i, &K.k0[i], &K.k1[i]);

  kFused<<<NB, NT>>>(emb, W1, b1, W2, b2, out, K);
}

// round 6
// speedup vs baseline: 1.7458x; 1.1448x over previous
#include <cuda_runtime.h>
#include <cstdint>

#define LSEQ   128
#define NSTEPS 10
#define NB     256     // grid blocks (must all be co-resident)
#define NT     256
#define NBAR   14      // exactly NBAR gridbar calls per kernel run (replay-safe wraparound)
#define NELEMS 262144

// ---------------- device scratch ----------------
__device__ float g_C[16 * 2048];        // chunk sums of W1 (8 rows each)
__device__ float g_pre1[4096 * 32];     // base hidden pre-activation (+b1)
__device__ float g_part[NSTEPS * NB];   // per-block rowsq partials, per step
__device__ float g_accout[128 * 64];    // final-gather acc rows (i = 0..127)
__device__ float g_err32[32];           // per-b steploss accumulations
__device__ float g_abspart[NB];
__device__ unsigned g_bar[NBAR];        // zero-init; self-resetting

struct Keys { unsigned k0[NSTEPS]; unsigned k1[NSTEPS]; };

// ---------------- threefry2x32 ----------------
#define TF_ROT(x, r) (((x) << (r)) | ((x) >> (32 - (r))))
__host__ __device__ __forceinline__ void tf2x32(unsigned k0, unsigned k1,
                                                unsigned x0, unsigned x1,
                                                unsigned* o0, unsigned* o1) {
  unsigned ks0 = k0, ks1 = k1, ks2 = k0 ^ k1 ^ 0x1BD11BDAu;
  x0 += ks0; x1 += ks1;
#define TF_R4(a,b,c,d) \
  x0 += x1; x1 = TF_ROT(x1,a); x1 ^= x0; \
  x0 += x1; x1 = TF_ROT(x1,b); x1 ^= x0; \
  x0 += x1; x1 = TF_ROT(x1,c); x1 ^= x0; \
  x0 += x1; x1 = TF_ROT(x1,d); x1 ^= x0;
  TF_R4(13,15,26,6)  x0 += ks1; x1 += ks2 + 1u;
  TF_R4(17,29,16,24) x0 += ks2; x1 += ks0 + 2u;
  TF_R4(13,15,26,6)  x0 += ks0; x1 += ks1 + 3u;
  TF_R4(17,29,16,24) x0 += ks1; x1 += ks2 + 4u;
  TF_R4(13,15,26,6)  x0 += ks2; x1 += ks0 + 5u;
#undef TF_R4
  *o0 = x0; *o1 = x1;
}

__device__ __forceinline__ unsigned tfxor(unsigned k0, unsigned k1, unsigned e) {
  unsigned o0, o1;
  tf2x32(k0, k1, 0u, e, &o0, &o1);
  return o0 ^ o1;
}

// bits -> uniform -> sqrt(2)*erfinv (XLA/Giles f32 polynomial)
__device__ __forceinline__ float bits_to_normal(unsigned bits) {
  float f = __uint_as_float((bits >> 9) | 0x3f800000u) - 1.0f;
  const float lo = __uint_as_float(0xBF7FFFFFu);
  float u = fmaxf(lo, f * 2.0f + lo);
  float w = -log1pf(-u * u);
  float p;
  if (w < 5.0f) {
    w -= 2.5f;
    p = 2.81022636e-08f;
    p = fmaf(p, w, 3.43273939e-07f);
    p = fmaf(p, w, -3.5233877e-06f);
    p = fmaf(p, w, -4.39150654e-06f);
    p = fmaf(p, w, 0.00021858087f);
    p = fmaf(p, w, -0.00125372503f);
    p = fmaf(p, w, -0.00417768164f);
    p = fmaf(p, w, 0.246640727f);
    p = fmaf(p, w, 1.50140941f);
  } else {
    w = sqrtf(w) - 3.0f;
    p = -0.000200214257f;
    p = fmaf(p, w, 0.000100950558f);
    p = fmaf(p, w, 0.00134934322f);
    p = fmaf(p, w, -0.00367342844f);
    p = fmaf(p, w, 0.00573950773f);
    p = fmaf(p, w, -0.0076224613f);
    p = fmaf(p, w, 0.00943887047f);
    p = fmaf(p, w, 1.00167406f);
    p = fmaf(p, w, 2.83297682f);
  }
  return 1.41421356237f * (p * u);
}

__device__ __forceinline__ float wred(float v) {
#pragma unroll
  for (int o = 16; o; o >>= 1) v += __shfl_xor_sync(0xffffffffu, v, o);
  return v;
}

// grid barrier with self-reset: at barrier k, block 0 zeroes slot (k-2) mod NBAR.
// With exactly NBAR barriers per run, slots 12/13 are reset by barriers 0/1 of the
// NEXT run, before first use — replay-safe under graph capture.
__device__ __forceinline__ void gridbar(int k) {
  __threadfence();
  __syncthreads();
  if (threadIdx.x == 0) {
    atomicAdd(&g_bar[k], 1u);
    while (*(volatile unsigned*)&g_bar[k] < NB) { }
    if (blockIdx.x == 0) {
      atomicExch(&g_bar[(k + NBAR - 2) % NBAR], 0u);
      __threadfence();
    }
  }
  __syncthreads();
}

// ---------------- the one fused kernel ----------------
__global__ void __launch_bounds__(NT, 2) kFused(
    const float* __restrict__ emb, const float* __restrict__ W1,
    const float* __restrict__ b1,  const float* __restrict__ W2,
    const float* __restrict__ b2,  float* __restrict__ out, Keys K) {
  __shared__ float sW[2048];   // W1 tile [d][h] for t
  __shared__ float sW2[2048];  // [h][d]
  __shared__ float sS[2048];   // prologue suffix sums (P1 only)
  __shared__ float sRed[256];
  __shared__ float sb2s[64];
  __shared__ float swts[32];

  const int p = blockIdx.x;
  const int tid = threadIdx.x;
  const int lane = tid & 31, w = tid >> 5;
  const int t = p & 127, half = p >> 7;

  for (int i = tid; i < 2048; i += NT) {
    sW[i]  = W1[t * 2048 + i];
    sW2[i] = W2[i];
  }
  if (tid < 64) sb2s[tid] = b2[tid];
  if (tid < 32) swts[tid] = W1[262144 + tid];

  // ---- P0: chunk sums C[c][q] = sum of W1 rows 8c..8c+7 ----
  if (p < 16) {
    for (int qq = tid; qq < 2048; qq += NT) {
      float s = 0.0f;
#pragma unroll
      for (int r = 0; r < 8; ++r) s += W1[(p * 8 + r) * 2048 + qq];
      __stcg(&g_C[p * 2048 + qq], s);
    }
  }
  gridbar(0);

  // ---- P1: S[j] suffix sums + pre1 rows for j = p ----
  if (p < 128) {
    const int j = p, cj = j >> 3;
    for (int qq = tid; qq < 2048; qq += NT) {
      float s = 0.0f;
      for (int c = cj + 1; c < 16; ++c) s += __ldcg(&g_C[c * 2048 + qq]);
      for (int tt = j + 1; tt < cj * 8 + 8; ++tt) s += W1[tt * 2048 + qq];
      sS[qq] = s;
    }
    __syncthreads();
    const int o = tid * 4;
    const int b = o >> 5, hh = o & 31;
    float v0 = b1[hh], v1 = b1[hh + 1], v2 = b1[hh + 2], v3 = b1[hh + 3];
    const float* er = emb + b * 8192 + j * 64;
#pragma unroll 8
    for (int d = 0; d < 64; ++d) {
      float ev = er[d];
      const float* sp = &sS[d * 32 + hh];
      v0 = fmaf(ev, sp[0], v0); v1 = fmaf(ev, sp[1], v1);
      v2 = fmaf(ev, sp[2], v2); v3 = fmaf(ev, sp[3], v3);
    }
    float* pp = &g_pre1[(j * 32 + b) * 32 + hh];
    pp[0] = v0; pp[1] = v1; pp[2] = v2; pp[3] = v3;
  }
  gridbar(1);

  // ---- per-warp row ownership: rows n0, n1 ----
  const int mm0 = half * 16 + 2 * w;
  const int n0 = t + 128 * mm0;
  const int n1 = n0 + 128;
  float pre0 = __ldcg(&g_pre1[n0 * 32 + lane]);
  float pre1r = __ldcg(&g_pre1[n1 * 32 + lane]);
  float a00 = 0.f, a01 = 0.f, a10 = 0.f, a11 = 0.f;
  const int b0 = n0 & 31, b1i = n1 & 31;
  const bool sp0 = (n0 == 1024 * (b0 & 3) + 33 * b0);
  const bool sp1 = (n1 == 1024 * (b1i & 3) + 33 * b1i);
  const bool f0 = ((n0 & 31) == (n0 >> 7));
  const bool f1 = ((n1 & 31) == (n1 >> 7));
  float err0 = 0.f, err1 = 0.f;
  const float sdt = 0.316227766016838f;

  for (int s = 0; s < NSTEPS; ++s) {
    const float tval = (float)s * 0.1f;
    // hidden: 4 accumulators per row (break FMA chain)
    float x0 = 0.f, x1 = 0.f, x2 = 0.f, x3 = 0.f;
    float y0 = 0.f, y1 = 0.f, y2 = 0.f, y3 = 0.f;
#pragma unroll
    for (int d = 0; d < 16; ++d) {
      float wv = sW[d * 32 + lane];
      x0 = fmaf(__shfl_sync(0xffffffffu, a00, d), wv, x0);
      y0 = fmaf(__shfl_sync(0xffffffffu, a10, d), wv, y0);
    }
#pragma unroll
    for (int d = 16; d < 32; ++d) {
      float wv = sW[d * 32 + lane];
      x1 = fmaf(__shfl_sync(0xffffffffu, a00, d), wv, x1);
      y1 = fmaf(__shfl_sync(0xffffffffu, a10, d), wv, y1);
    }
#pragma unroll
    for (int d = 0; d < 16; ++d) {
      float wv = sW[(32 + d) * 32 + lane];
      x2 = fmaf(__shfl_sync(0xffffffffu, a01, d), wv, x2);
      y2 = fmaf(__shfl_sync(0xffffffffu, a11, d), wv, y2);
    }
#pragma unroll
    for (int d = 16; d < 32; ++d) {
      float wv = sW[(32 + d) * 32 + lane];
      x3 = fmaf(__shfl_sync(0xffffffffu, a01, d), wv, x3);
      y3 = fmaf(__shfl_sync(0xffffffffu, a11, d), wv, y3);
    }
    float base = pre0 + tval * swts[lane];
    float h0 = fmaxf(base + ((x0 + x1) + (x2 + x3)), 0.0f);
    base = pre1r + tval * swts[lane];
    float h1 = fmaxf(base + ((y0 + y1) + (y2 + y3)), 0.0f);

    // score: 2 accumulators per output half
    float p00 = 0.f, q00 = 0.f, p01 = 0.f, q01 = 0.f;
    float p10 = 0.f, q10 = 0.f, p11 = 0.f, q11 = 0.f;
#pragma unroll
    for (int hh = 0; hh < 16; ++hh) {
      float w0 = sW2[hh * 64 + lane], w1 = sW2[hh * 64 + 32 + lane];
      float hv0 = __shfl_sync(0xffffffffu, h0, hh);
      float hv1 = __shfl_sync(0xffffffffu, h1, hh);
      p00 = fmaf(hv0, w0, p00); p01 = fmaf(hv0, w1, p01);
      p10 = fmaf(hv1, w0, p10); p11 = fmaf(hv1, w1, p11);
    }
#pragma unroll
    for (int hh = 16; hh < 32; ++hh) {
      float w0 = sW2[hh * 64 + lane], w1 = sW2[hh * 64 + 32 + lane];
      float hv0 = __shfl_sync(0xffffffffu, h0, hh);
      float hv1 = __shfl_sync(0xffffffffu, h1, hh);
      q00 = fmaf(hv0, w0, q00); q01 = fmaf(hv0, w1, q01);
      q10 = fmaf(hv1, w0, q10); q11 = fmaf(hv1, w1, q11);
    }
    const float s00 = sb2s[lane] + (p00 + q00);
    const float s01 = sb2s[32 + lane] + (p01 + q01);
    const float s10 = sb2s[lane] + (p10 + q10);
    const float s11 = sb2s[32 + lane] + (p11 + q11);

    // publish block rowsq partial
    float rq = wred(fmaf(s00, s00, fmaf(s01, s01, fmaf(s10, s10, s11 * s11))));
    if (lane == 0) sRed[w] = rq;
    __syncthreads();
    if (tid == 0) {
      float bp = ((sRed[0] + sRed[1]) + (sRed[2] + sRed[3])) +
                 ((sRed[4] + sRed[5]) + (sRed[6] + sRed[7]));
      __stcg(&g_part[s * NB + p], bp);
    }

    // noise for this step — independent of snorm; overlaps barrier
    const unsigned k0 = K.k0[s], k1 = K.k1[s];
    const float dW00 = bits_to_normal(tfxor(k0, k1, (unsigned)(n0 * 64 + lane))) * sdt;
    const float dW01 = bits_to_normal(tfxor(k0, k1, (unsigned)(n0 * 64 + 32 + lane))) * sdt;
    const float dW10 = bits_to_normal(tfxor(k0, k1, (unsigned)(n1 * 64 + lane))) * sdt;
    const float dW11 = bits_to_normal(tfxor(k0, k1, (unsigned)(n1 * 64 + 32 + lane))) * sdt;

    gridbar(2 + s);

    // snorm: warp 0 reduces 256 partials (8 per lane), 1 sync
    if (w == 0) {
      const float* gp = &g_part[s * NB];
      float v0s = 0.f, v1s = 0.f;
#pragma unroll
      for (int i = 0; i < 4; ++i) v0s += __ldcg(&gp[lane * 8 + i]);
#pragma unroll
      for (int i = 4; i < 8; ++i) v1s += __ldcg(&gp[lane * 8 + i]);
      float v = wred(v0s + v1s);
      if (lane == 0) sRed[0] = v;
    }
    __syncthreads();
    const float snorm = sqrtf(sRed[0]);

    a00 += 0.5f * s00 * 0.1f + snorm * dW00;
    a01 += 0.5f * s01 * 0.1f + snorm * dW01;
    a10 += 0.5f * s10 * 0.1f + snorm * dW10;
    a11 += 0.5f * s11 * 0.1f + snorm * dW11;

    if (sp0) {
      float sq = wred(fmaf(a00, a00, a01 * a01));
      if (lane == 0) err0 += sq * (1.0f / 64.0f);
    }
    if (sp1) {
      float sq = wred(fmaf(a10, a10, a11 * a11));
      if (lane == 0) err1 += sq * (1.0f / 64.0f);
    }
  }

  // publish per-b step errors and final-gather acc rows
  if (sp0 && lane == 0) __stcg(&g_err32[b0], err0);
  if (sp1 && lane == 0) __stcg(&g_err32[b1i], err1);
  if (f0) {
    __stcg(&g_accout[(n0 >> 5) * 64 + lane], a00);
    __stcg(&g_accout[(n0 >> 5) * 64 + 32 + lane], a01);
  }
  if (f1) {
    __stcg(&g_accout[(n1 >> 5) * 64 + lane], a10);
    __stcg(&g_accout[(n1 >> 5) * 64 + 32 + lane], a11);
  }
  gridbar(12);

  // ---- finale sweep: out[b,i,d] + |emb - out| partials ----
  {
    const int base = p * 1024 + tid * 4;
    const int bb = base >> 13;
    const int ii = (base >> 6) & 127;
    const int jj = ii >> 2;
    const bool he = ii < 32 * (ii & 3) + bb;
    const bool ha = (jj == bb);
    float loc = 0.0f;
#pragma unroll
    for (int q = 0; q < 4; ++q) {
      const int d = (base & 63) + q;
      float v = 0.0f;
      if (he) v = emb[jj * 8192 + ii * 64 + d];
      if (ha) v += __ldcg(&g_accout[ii * 64 + d]);
      out[base + q] = v;
      loc += fabsf(emb[base + q] - v);
    }
    loc = wred(loc);
    if (lane == 0) sRed[w] = loc;
    __syncthreads();
    if (tid == 0) {
      float bp = ((sRed[0] + sRed[1]) + (sRed[2] + sRed[3])) +
                 ((sRed[4] + sRed[5]) + (sRed[6] + sRed[7]));
      __stcg(&g_abspart[p], bp);
    }
  }
  gridbar(13);

  // block 0: parallel final reduction
  if (p == 0) {
    sRed[tid] = __ldcg(&g_abspart[tid]);
    __syncthreads();
    for (int off = 128; off; off >>= 1) {
      if (tid < off) sRed[tid] += sRed[tid + off];
      __syncthreads();
    }
    float sl = 0.0f;
    if (tid < 32) sl = wred(__ldcg(&g_err32[tid]));
    if (tid == 0) {
      out[NELEMS] = sl;                            // step_loss
      out[NELEMS + 1] = sRed[0] * (1.0f / 262144.0f);  // sequence_loss
    }
  }
}

// ---------------- launch ----------------
extern "C" void kernel_launch(void* const* d_in, const int* in_sizes, int n_in,
                              void* d_out, int out_size) {
  const float* emb = (const float*)d_in[0];
  const float* W1  = (const float*)d_in[1];
  const float* b1  = (const float*)d_in[2];
  const float* W2  = (const float*)d_in[3];
  const float* b2  = (const float*)d_in[4];
  float* out = (float*)d_out;

  Keys K;
  for (int i = 0; i < NSTEPS; ++i)
    tf2x32(0u, 42u, 0u, (unsigned)i, &K.k0[i], &K.k1[i]);

  kFused<<<NB, NT>>>(emb, W1, b1, W2, b2, out, K);
}

// round 7
// speedup vs baseline: 1.9540x; 1.1192x over previous
#include <cuda_runtime.h>
#include <cstdint>

#define NSTEPS 10
#define NB     512     // grid blocks (all co-resident: 148 SMs x 4 blocks = 592 slots)
#define NT     256
#define NBAR   14      // 2 prologue + 10 steps + 2 finale; slot k reset by barrier (k+1)%NBAR
#define NELEMS 262144
#define MASK52 ((1ull << 52) - 1ull)
#define CNT1   (1ull << 52)

// ---------------- device scratch ----------------
__device__ float g_C[16 * 2048];            // chunk sums of W1 (8 rows each)
__device__ float g_pre1[4096 * 32];         // base hidden pre-activation (+b1)
__device__ float g_accout[128 * 64];        // final-gather acc rows
__device__ float g_err32[32];               // per-b steploss accumulations
__device__ float g_abspart[NB];
__device__ unsigned long long g_sync[NBAR]; // packed (count<<52 | fixedpoint sum); self-resetting

struct Keys { unsigned k0[NSTEPS]; unsigned k1[NSTEPS]; };

// ---------------- threefry2x32 ----------------
#define TF_ROT(x, r) (((x) << (r)) | ((x) >> (32 - (r))))
__host__ __device__ __forceinline__ void tf2x32(unsigned k0, unsigned k1,
                                                unsigned x0, unsigned x1,
                                                unsigned* o0, unsigned* o1) {
  unsigned ks0 = k0, ks1 = k1, ks2 = k0 ^ k1 ^ 0x1BD11BDAu;
  x0 += ks0; x1 += ks1;
#define TF_R4(a,b,c,d) \
  x0 += x1; x1 = TF_ROT(x1,a); x1 ^= x0; \
  x0 += x1; x1 = TF_ROT(x1,b); x1 ^= x0; \
  x0 += x1; x1 = TF_ROT(x1,c); x1 ^= x0; \
  x0 += x1; x1 = TF_ROT(x1,d); x1 ^= x0;
  TF_R4(13,15,26,6)  x0 += ks1; x1 += ks2 + 1u;
  TF_R4(17,29,16,24) x0 += ks2; x1 += ks0 + 2u;
  TF_R4(13,15,26,6)  x0 += ks0; x1 += ks1 + 3u;
  TF_R4(17,29,16,24) x0 += ks1; x1 += ks2 + 4u;
  TF_R4(13,15,26,6)  x0 += ks2; x1 += ks0 + 5u;
#undef TF_R4
  *o0 = x0; *o1 = x1;
}

__device__ __forceinline__ unsigned tfxor(unsigned k0, unsigned k1, unsigned e) {
  unsigned o0, o1;
  tf2x32(k0, k1, 0u, e, &o0, &o1);
  return o0 ^ o1;
}

// bits -> uniform -> sqrt(2)*erfinv (XLA/Giles f32 polynomial)
__device__ __forceinline__ float bits_to_normal(unsigned bits) {
  float f = __uint_as_float((bits >> 9) | 0x3f800000u) - 1.0f;
  const float lo = __uint_as_float(0xBF7FFFFFu);
  float u = fmaxf(lo, f * 2.0f + lo);
  float w = -log1pf(-u * u);
  float p;
  if (w < 5.0f) {
    w -= 2.5f;
    p = 2.81022636e-08f;
    p = fmaf(p, w, 3.43273939e-07f);
    p = fmaf(p, w, -3.5233877e-06f);
    p = fmaf(p, w, -4.39150654e-06f);
    p = fmaf(p, w, 0.00021858087f);
    p = fmaf(p, w, -0.00125372503f);
    p = fmaf(p, w, -0.00417768164f);
    p = fmaf(p, w, 0.246640727f);
    p = fmaf(p, w, 1.50140941f);
  } else {
    w = sqrtf(w) - 3.0f;
    p = -0.000200214257f;
    p = fmaf(p, w, 0.000100950558f);
    p = fmaf(p, w, 0.00134934322f);
    p = fmaf(p, w, -0.00367342844f);
    p = fmaf(p, w, 0.00573950773f);
    p = fmaf(p, w, -0.0076224613f);
    p = fmaf(p, w, 0.00943887047f);
    p = fmaf(p, w, 1.00167406f);
    p = fmaf(p, w, 2.83297682f);
  }
  return 1.41421356237f * (p * u);
}

__device__ __forceinline__ float wred(float v) {
#pragma unroll
  for (int o = 16; o; o >>= 1) v += __shfl_xor_sync(0xffffffffu, v, o);
  return v;
}

// Fused barrier: tid0 adds (payload | CNT1) to slot k, polls count==NB, returns
// packed final value. Last arriver (by return value) resets slot (k-1)%NBAR —
// safe: all blocks exited poll of k-1 before arriving at k. Replay-safe: slot 13
// is reset by barrier 0 of the NEXT run, before its first use there.
__device__ __forceinline__ unsigned long long arrive_poll(int k, unsigned long long payload) {
  unsigned long long add = payload + CNT1;
  unsigned long long old = atomicAdd(&g_sync[k], add);
  if ((old >> 52) == (unsigned long long)(NB - 1)) {
    *((volatile unsigned long long*)&g_sync[(k + NBAR - 1) % NBAR]) = 0ull;
    return old + add;   // last arriver: final value, no poll
  }
  unsigned long long v;
  do { v = *((volatile unsigned long long*)&g_sync[k]); } while ((v >> 52) < (unsigned long long)NB);
  return v;
}

// ---------------- the one fused kernel ----------------
__global__ void __launch_bounds__(NT, 4) kFused(
    const float* __restrict__ emb, const float* __restrict__ W1,
    const float* __restrict__ b1,  const float* __restrict__ W2,
    const float* __restrict__ b2,  float* __restrict__ out, Keys K) {
  __shared__ float sW[2048];   // W1 tile [d][h] for this block's t
  __shared__ float sW2[2048];  // [h][d]
  __shared__ float sS[2048];   // prologue suffix sums (P1 blocks only)
  __shared__ float sRed[256];
  __shared__ float sb2s[64];
  __shared__ float swts[32];

  const int p = blockIdx.x;
  const int tid = threadIdx.x;
  const int lane = tid & 31, w = tid >> 5;
  const int t = p & 127;

  for (int i = tid; i < 2048; i += NT) {
    sW[i]  = W1[t * 2048 + i];
    sW2[i] = W2[i];
  }
  if (tid < 64) sb2s[tid] = b2[tid];
  if (tid < 32) swts[tid] = W1[262144 + tid];

  // ---- P0: chunk sums C[c][q] = sum of W1 rows 8c..8c+7 ----
  if (p < 16) {
    for (int qq = tid; qq < 2048; qq += NT) {
      float s = 0.0f;
#pragma unroll
      for (int r = 0; r < 8; ++r) s += W1[(p * 8 + r) * 2048 + qq];
      __stcg(&g_C[p * 2048 + qq], s);
    }
    __threadfence();
  }
  __syncthreads();
  if (tid == 0) { arrive_poll(0, 0ull); }
  __syncthreads();
  __threadfence();

  // ---- P1: S[j] suffix sums + pre1 rows for j = p (blocks 0..127) ----
  if (p < 128) {
    const int j = p, cj = j >> 3;
    for (int qq = tid; qq < 2048; qq += NT) {
      float s = 0.0f;
      for (int c = cj + 1; c < 16; ++c) s += __ldcg(&g_C[c * 2048 + qq]);
      for (int tt = j + 1; tt < cj * 8 + 8; ++tt) s += W1[tt * 2048 + qq];
      sS[qq] = s;
    }
    __syncthreads();
    const int o = tid * 4;
    const int b = o >> 5, hh = o & 31;
    float v0 = b1[hh], v1 = b1[hh + 1], v2 = b1[hh + 2], v3 = b1[hh + 3];
    const float* er = emb + b * 8192 + j * 64;
#pragma unroll 8
    for (int d = 0; d < 64; ++d) {
      float ev = er[d];
      const float* sp = &sS[d * 32 + hh];
      v0 = fmaf(ev, sp[0], v0); v1 = fmaf(ev, sp[1], v1);
      v2 = fmaf(ev, sp[2], v2); v3 = fmaf(ev, sp[3], v3);
    }
    float* pp = &g_pre1[(j * 32 + b) * 32 + hh];
    pp[0] = v0; pp[1] = v1; pp[2] = v2; pp[3] = v3;
    __threadfence();
  }
  __syncthreads();
  if (tid == 0) { arrive_poll(1, 0ull); }
  __syncthreads();
  __threadfence();

  // ---- one row per warp: n = t + 128*m, m = (p>>7)*8 + w ----
  const int m = (p >> 7) * 8 + w;
  const int n = t + 128 * m;
  const float pre = __ldcg(&g_pre1[n * 32 + lane]);
  float a0 = 0.f, a1 = 0.f;
  const int b = n & 31;
  const bool sp = (n == 1024 * (b & 3) + 33 * b);   // steploss-special row
  const bool fg = ((n & 31) == (n >> 7));           // final-gather row
  float err = 0.f;
  const float sdt = 0.316227766016838f;

  for (int s = 0; s < NSTEPS; ++s) {
    const float tval = (float)s * 0.1f;
    // hidden (h = relu(pre + t*wt + acc.W1tile)), 4 accumulator chains
    float x0 = 0.f, x1 = 0.f, x2 = 0.f, x3 = 0.f;
#pragma unroll
    for (int d = 0; d < 16; ++d)
      x0 = fmaf(__shfl_sync(0xffffffffu, a0, d), sW[d * 32 + lane], x0);
#pragma unroll
    for (int d = 16; d < 32; ++d)
      x1 = fmaf(__shfl_sync(0xffffffffu, a0, d), sW[d * 32 + lane], x1);
#pragma unroll
    for (int d = 0; d < 16; ++d)
      x2 = fmaf(__shfl_sync(0xffffffffu, a1, d), sW[(32 + d) * 32 + lane], x2);
#pragma unroll
    for (int d = 16; d < 32; ++d)
      x3 = fmaf(__shfl_sync(0xffffffffu, a1, d), sW[(32 + d) * 32 + lane], x3);
    const float h = fmaxf(pre + tval * swts[lane] + ((x0 + x1) + (x2 + x3)), 0.0f);

    // score (s0,s1), 2 chains each
    float p0 = 0.f, q0 = 0.f, p1 = 0.f, q1 = 0.f;
#pragma unroll
    for (int hh = 0; hh < 16; ++hh) {
      float hv = __shfl_sync(0xffffffffu, h, hh);
      p0 = fmaf(hv, sW2[hh * 64 + lane], p0);
      p1 = fmaf(hv, sW2[hh * 64 + 32 + lane], p1);
    }
#pragma unroll
    for (int hh = 16; hh < 32; ++hh) {
      float hv = __shfl_sync(0xffffffffu, h, hh);
      q0 = fmaf(hv, sW2[hh * 64 + lane], q0);
      q1 = fmaf(hv, sW2[hh * 64 + 32 + lane], q1);
    }
    const float s0 = sb2s[lane] + (p0 + q0);
    const float s1 = sb2s[32 + lane] + (p1 + q1);

    // block rowsq partial -> fused barrier
    float rq = wred(fmaf(s0, s0, s1 * s1));
    if (lane == 0) sRed[w] = rq;
    __syncthreads();
    if (tid == 0) {
      float bp = ((sRed[0] + sRed[1]) + (sRed[2] + sRed[3])) +
                 ((sRed[4] + sRed[5]) + (sRed[6] + sRed[7]));
      unsigned long long pay = (unsigned long long)(bp * 4294967296.0f);
      unsigned long long v = arrive_poll(2 + s, pay);
      sRed[0] = (float)((double)(v & MASK52) * (1.0 / 4294967296.0));
    }
    // noise overlaps tid0's barrier round-trip
    const unsigned k0 = K.k0[s], k1 = K.k1[s];
    const float dW0 = bits_to_normal(tfxor(k0, k1, (unsigned)(n * 64 + lane))) * sdt;
    const float dW1 = bits_to_normal(tfxor(k0, k1, (unsigned)(n * 64 + 32 + lane))) * sdt;
    __syncthreads();
    const float snorm = sqrtf(sRed[0]);

    a0 += 0.05f * s0 + snorm * dW0;
    a1 += 0.05f * s1 + snorm * dW1;

    if (sp) {
      float sq = wred(fmaf(a0, a0, a1 * a1));
      if (lane == 0) err += sq * (1.0f / 64.0f);
    }
  }

  // publish per-b step errors and final-gather acc rows
  if (sp && lane == 0) __stcg(&g_err32[b], err);
  if (fg) {
    __stcg(&g_accout[(n >> 5) * 64 + lane], a0);
    __stcg(&g_accout[(n >> 5) * 64 + 32 + lane], a1);
  }
  __threadfence();
  __syncthreads();
  if (tid == 0) { arrive_poll(12, 0ull); }
  __syncthreads();
  __threadfence();

  // ---- finale sweep: out[b,i,d] + |emb - out| partials (2 elems/thread) ----
  {
    const int base = p * 512 + tid * 2;
    const int bb = base >> 13;
    const int ii = (base >> 6) & 127;
    const int jj = ii >> 2;
    const bool he = ii < 32 * (ii & 3) + bb;
    const bool ha = (jj == bb);
    float loc = 0.0f;
#pragma unroll
    for (int q = 0; q < 2; ++q) {
      const int d = (base & 63) + q;
      float v = 0.0f;
      if (he) v = emb[jj * 8192 + ii * 64 + d];
      if (ha) v += __ldcg(&g_accout[ii * 64 + d]);
      out[base + q] = v;
      loc += fabsf(emb[base + q] - v);
    }
    loc = wred(loc);
    if (lane == 0) sRed[w] = loc;
    __syncthreads();
    if (tid == 0) {
      float bp = ((sRed[0] + sRed[1]) + (sRed[2] + sRed[3])) +
                 ((sRed[4] + sRed[5]) + (sRed[6] + sRed[7]));
      __stcg(&g_abspart[p], bp);
      __threadfence();
      arrive_poll(13, 0ull);
    }
    __syncthreads();
  }

  // block 0: parallel final reduction
  if (p == 0) {
    __threadfence();
    sRed[tid] = __ldcg(&g_abspart[tid]) + __ldcg(&g_abspart[tid + 256]);
    __syncthreads();
    for (int off = 128; off; off >>= 1) {
      if (tid < off) sRed[tid] += sRed[tid + off];
      __syncthreads();
    }
    float sl = 0.0f;
    if (tid < 32) sl = wred(__ldcg(&g_err32[tid]));
    if (tid == 0) {
      out[NELEMS] = sl;                                // step_loss
      out[NELEMS + 1] = sRed[0] * (1.0f / 262144.0f);  // sequence_loss
    }
  }
}

// ---------------- launch ----------------
extern "C" void kernel_launch(void* const* d_in, const int* in_sizes, int n_in,
                              void* d_out, int out_size) {
  const float* emb = (const float*)d_in[0];
  const float* W1  = (const float*)d_in[1];
  const float* b1  = (const float*)d_in[2];
  const float* W2  = (const float*)d_in[3];
  const float* b2  = (const float*)d_in[4];
  float* out = (float*)d_out;

  Keys K;
  for (int i = 0; i < NSTEPS; ++i)
    tf2x32(0u, 42u, 0u, (unsigned)i, &K.k0[i], &K.k1[i]);

  kFused<<<NB, NT>>>(emb, W1, b1, W2, b2, out, K);
}

// round 8
// speedup vs baseline: 2.0420x; 1.0451x over previous
#include <cuda_runtime.h>
#include <cstdint>

#define NSTEPS 10
#define NB     512     // grid blocks (all co-resident: 148 SMs x 4 blocks = 592 slots)
#define NT     256
#define NBAR   14      // exactly NBAR barriers per run; slot k reset by last arriver of k+1 (mod)
#define NELEMS 262144
#define MASK52 ((1ull << 52) - 1ull)
#define CNT1   (1ull << 52)
#define WSTRIDE 76     // smem row stride (floats): float4-aligned, conflict-free (12l+4k pattern)

// ---------------- device scratch ----------------
__device__ float g_C[16 * 2048];            // chunk sums of W1 (8 rows each)
__device__ float g_pre1[4096 * 32];         // base hidden pre-activation (+b1)
__device__ float g_accout[128 * 64];        // final-gather acc rows
__device__ float g_err32[32];               // per-b steploss accumulations
__device__ float g_abspart[NB];
__device__ unsigned long long g_sync[NBAR]; // packed (count<<52 | fixedpoint sum); self-resetting

struct Keys { unsigned k0[NSTEPS]; unsigned k1[NSTEPS]; };

// ---------------- threefry2x32 ----------------
#define TF_ROT(x, r) (((x) << (r)) | ((x) >> (32 - (r))))
__host__ __device__ __forceinline__ void tf2x32(unsigned k0, unsigned k1,
                                                unsigned x0, unsigned x1,
                                                unsigned* o0, unsigned* o1) {
  unsigned ks0 = k0, ks1 = k1, ks2 = k0 ^ k1 ^ 0x1BD11BDAu;
  x0 += ks0; x1 += ks1;
#define TF_R4(a,b,c,d) \
  x0 += x1; x1 = TF_ROT(x1,a); x1 ^= x0; \
  x0 += x1; x1 = TF_ROT(x1,b); x1 ^= x0; \
  x0 += x1; x1 = TF_ROT(x1,c); x1 ^= x0; \
  x0 += x1; x1 = TF_ROT(x1,d); x1 ^= x0;
  TF_R4(13,15,26,6)  x0 += ks1; x1 += ks2 + 1u;
  TF_R4(17,29,16,24) x0 += ks2; x1 += ks0 + 2u;
  TF_R4(13,15,26,6)  x0 += ks0; x1 += ks1 + 3u;
  TF_R4(17,29,16,24) x0 += ks1; x1 += ks2 + 4u;
  TF_R4(13,15,26,6)  x0 += ks2; x1 += ks0 + 5u;
#undef TF_R4
  *o0 = x0; *o1 = x1;
}

__device__ __forceinline__ unsigned tfxor(unsigned k0, unsigned k1, unsigned e) {
  unsigned o0, o1;
  tf2x32(k0, k1, 0u, e, &o0, &o1);
  return o0 ^ o1;
}

// bits -> uniform -> sqrt(2)*erfinv (XLA/Giles f32 polynomial)
__device__ __forceinline__ float bits_to_normal(unsigned bits) {
  float f = __uint_as_float((bits >> 9) | 0x3f800000u) - 1.0f;
  const float lo = __uint_as_float(0xBF7FFFFFu);
  float u = fmaxf(lo, f * 2.0f + lo);
  float w = -log1pf(-u * u);
  float p;
  if (w < 5.0f) {
    w -= 2.5f;
    p = 2.81022636e-08f;
    p = fmaf(p, w, 3.43273939e-07f);
    p = fmaf(p, w, -3.5233877e-06f);
    p = fmaf(p, w, -4.39150654e-06f);
    p = fmaf(p, w, 0.00021858087f);
    p = fmaf(p, w, -0.00125372503f);
    p = fmaf(p, w, -0.00417768164f);
    p = fmaf(p, w, 0.246640727f);
    p = fmaf(p, w, 1.50140941f);
  } else {
    w = sqrtf(w) - 3.0f;
    p = -0.000200214257f;
    p = fmaf(p, w, 0.000100950558f);
    p = fmaf(p, w, 0.00134934322f);
    p = fmaf(p, w, -0.00367342844f);
    p = fmaf(p, w, 0.00573950773f);
    p = fmaf(p, w, -0.0076224613f);
    p = fmaf(p, w, 0.00943887047f);
    p = fmaf(p, w, 1.00167406f);
    p = fmaf(p, w, 2.83297682f);
  }
  return 1.41421356237f * (p * u);
}

__device__ __forceinline__ float wred(float v) {
#pragma unroll
  for (int o = 16; o; o >>= 1) v += __shfl_xor_sync(0xffffffffu, v, o);
  return v;
}

// Fused barrier+sum: tid0 adds (payload | CNT1) to slot k, polls count==NB.
// Last arriver resets slot (k-1)%NBAR (all blocks have left its poll).
// Replay-safe: slot 13 is reset by barrier 0 of the next launch, pre-use.
__device__ __forceinline__ unsigned long long arrive_poll(int k, unsigned long long payload) {
  unsigned long long add = payload + CNT1;
  unsigned long long old = atomicAdd(&g_sync[k], add);
  if ((old >> 52) == (unsigned long long)(NB - 1)) {
    *((volatile unsigned long long*)&g_sync[(k + NBAR - 1) % NBAR]) = 0ull;
    return old + add;
  }
  unsigned long long v;
  do { v = *((volatile unsigned long long*)&g_sync[k]); } while ((v >> 52) < (unsigned long long)NB);
  return v;
}

// ---------------- the one fused kernel ----------------
__global__ void __launch_bounds__(NT, 4) kFused(
    const float* __restrict__ emb, const float* __restrict__ W1,
    const float* __restrict__ b1,  const float* __restrict__ W2,
    const float* __restrict__ b2,  float* __restrict__ out, Keys K) {
  __shared__ __align__(16) float sWT[32 * WSTRIDE];   // W1 tile transposed: [h][d]
  __shared__ __align__(16) union {
    float S[2048];                                    // prologue suffix sums
    float W2T[64 * WSTRIDE];                          // W2 transposed: [c][hh]
  } U;
  __shared__ __align__(16) float sAcc[8][64];         // per-warp acc staging
  __shared__ __align__(16) float sH[8][32];           // per-warp hidden staging
  __shared__ float sRed[256];
  __shared__ float sb2s[64];
  __shared__ float swts[32];

  const int p = blockIdx.x;
  const int tid = threadIdx.x;
  const int lane = tid & 31, w = tid >> 5;
  const int t = p & 127;

  // W1 tile transposed: sWT[h][d] = W1[t*2048 + d*32 + h]
  for (int i = tid; i < 2048; i += NT)
    sWT[(i & 31) * WSTRIDE + (i >> 5)] = W1[t * 2048 + i];
  if (tid < 64) sb2s[tid] = b2[tid];
  if (tid < 32) swts[tid] = W1[262144 + tid];

  // ---- P0: chunk sums C[c][q] = sum of W1 rows 8c..8c+7 ----
  if (p < 16) {
    for (int qq = tid; qq < 2048; qq += NT) {
      float s = 0.0f;
#pragma unroll
      for (int r = 0; r < 8; ++r) s += W1[(p * 8 + r) * 2048 + qq];
      __stcg(&g_C[p * 2048 + qq], s);
    }
    __threadfence();
  }
  __syncthreads();
  if (tid == 0) { arrive_poll(0, 0ull); }
  __syncthreads();
  __threadfence();

  // ---- P1: S[j] suffix sums + pre1 rows for j = p (blocks 0..127) ----
  if (p < 128) {
    const int j = p, cj = j >> 3;
    for (int qq = tid; qq < 2048; qq += NT) {
      float s = 0.0f;
      for (int c = cj + 1; c < 16; ++c) s += __ldcg(&g_C[c * 2048 + qq]);
      for (int tt = j + 1; tt < cj * 8 + 8; ++tt) s += W1[tt * 2048 + qq];
      U.S[qq] = s;
    }
    __syncthreads();
    const int o = tid * 4;
    const int b = o >> 5, hh = o & 31;
    float v0 = b1[hh], v1 = b1[hh + 1], v2 = b1[hh + 2], v3 = b1[hh + 3];
    const float* er = emb + b * 8192 + j * 64;
#pragma unroll 8
    for (int d = 0; d < 64; ++d) {
      float ev = er[d];
      const float* sp = &U.S[d * 32 + hh];
      v0 = fmaf(ev, sp[0], v0); v1 = fmaf(ev, sp[1], v1);
      v2 = fmaf(ev, sp[2], v2); v3 = fmaf(ev, sp[3], v3);
    }
    float* pp = &g_pre1[(j * 32 + b) * 32 + hh];
    pp[0] = v0; pp[1] = v1; pp[2] = v2; pp[3] = v3;
    __threadfence();
  }
  __syncthreads();
  if (tid == 0) { arrive_poll(1, 0ull); }
  __syncthreads();
  __threadfence();

  // W2 transposed (overlays sS, safe after barrier 1): sW2T[c][hh] = W2[hh*64+c]
  for (int i = tid; i < 2048; i += NT)
    U.W2T[(i & 63) * WSTRIDE + (i >> 6)] = W2[i];
  __syncthreads();

  // ---- one row per warp: n = t + 128*m, m = (p>>7)*8 + w ----
  const int m = (p >> 7) * 8 + w;
  const int n = t + 128 * m;
  const float pre = __ldcg(&g_pre1[n * 32 + lane]);
  float a0 = 0.f, a1 = 0.f;
  const int b = n & 31;
  const bool sp = (n == 1024 * (b & 3) + 33 * b);   // steploss-special row
  const bool fg = ((n & 31) == (n >> 7));           // final-gather row
  float err = 0.f;
  const float sdt = 0.316227766016838f;

  const float4* wtRow = (const float4*)&sWT[lane * WSTRIDE];          // 16 chunks of d
  const float4* w2Row0 = (const float4*)&U.W2T[lane * WSTRIDE];       // 8 chunks of hh
  const float4* w2Row1 = (const float4*)&U.W2T[(32 + lane) * WSTRIDE];
  const float4* accV = (const float4*)&sAcc[w][0];
  const float4* hV = (const float4*)&sH[w][0];

  for (int s = 0; s < NSTEPS; ++s) {
    const float tval = (float)s * 0.1f;
    // stage acc to per-warp smem
    sAcc[w][lane] = a0;
    sAcc[w][32 + lane] = a1;
    __syncwarp();

    // hidden: h[lane] = relu(pre + t*wt + sum_d acc[d]*W1t[d][lane]); vectorized
    float x0 = 0.f, x1 = 0.f, x2 = 0.f, x3 = 0.f;
#pragma unroll
    for (int k = 0; k < 16; ++k) {
      const float4 av = accV[k];      // broadcast
      const float4 wv = wtRow[k];     // conflict-free float4
      x0 = fmaf(av.x, wv.x, x0);
      x1 = fmaf(av.y, wv.y, x1);
      x2 = fmaf(av.z, wv.z, x2);
      x3 = fmaf(av.w, wv.w, x3);
    }
    const float h = fmaxf(pre + tval * swts[lane] + ((x0 + x1) + (x2 + x3)), 0.0f);
    sH[w][lane] = h;
    __syncwarp();

    // score: s0[lane], s1[lane]; vectorized over hh
    float p0 = 0.f, q0 = 0.f, p1 = 0.f, q1 = 0.f;
#pragma unroll
    for (int k = 0; k < 8; ++k) {
      const float4 hv = hV[k];        // broadcast
      const float4 wa = w2Row0[k];
      const float4 wb = w2Row1[k];
      p0 = fmaf(hv.x, wa.x, p0); q0 = fmaf(hv.y, wa.y, q0);
      p0 = fmaf(hv.z, wa.z, p0); q0 = fmaf(hv.w, wa.w, q0);
      p1 = fmaf(hv.x, wb.x, p1); q1 = fmaf(hv.y, wb.y, q1);
      p1 = fmaf(hv.z, wb.z, p1); q1 = fmaf(hv.w, wb.w, q1);
    }
    const float s0 = sb2s[lane] + (p0 + q0);
    const float s1 = sb2s[32 + lane] + (p1 + q1);

    // block rowsq partial -> fused barrier
    float rq = wred(fmaf(s0, s0, s1 * s1));
    if (lane == 0) sRed[w] = rq;
    __syncthreads();
    if (tid == 0) {
      float bp = ((sRed[0] + sRed[1]) + (sRed[2] + sRed[3])) +
                 ((sRed[4] + sRed[5]) + (sRed[6] + sRed[7]));
      unsigned long long pay = (unsigned long long)(bp * 4294967296.0f);
      unsigned long long v = arrive_poll(2 + s, pay);
      sRed[0] = (float)((double)(v & MASK52) * (1.0 / 4294967296.0));
    }
    // noise overlaps tid0's barrier round-trip
    const unsigned k0 = K.k0[s], k1 = K.k1[s];
    const float dW0 = bits_to_normal(tfxor(k0, k1, (unsigned)(n * 64 + lane))) * sdt;
    const float dW1 = bits_to_normal(tfxor(k0, k1, (unsigned)(n * 64 + 32 + lane))) * sdt;
    __syncthreads();
    const float snorm = sqrtf(sRed[0]);

    a0 += 0.05f * s0 + snorm * dW0;
    a1 += 0.05f * s1 + snorm * dW1;

    if (sp) {
      float sq = wred(fmaf(a0, a0, a1 * a1));
      if (lane == 0) err += sq * (1.0f / 64.0f);
    }
  }

  // publish per-b step errors and final-gather acc rows
  if (sp && lane == 0) __stcg(&g_err32[b], err);
  if (fg) {
    __stcg(&g_accout[(n >> 5) * 64 + lane], a0);
    __stcg(&g_accout[(n >> 5) * 64 + 32 + lane], a1);
  }
  __threadfence();
  __syncthreads();
  if (tid == 0) { arrive_poll(12, 0ull); }
  __syncthreads();
  __threadfence();

  // ---- finale sweep: out[b,i,d] + |emb - out| partials (2 elems/thread) ----
  {
    const int base = p * 512 + tid * 2;
    const int bb = base >> 13;
    const int ii = (base >> 6) & 127;
    const int jj = ii >> 2;
    const bool he = ii < 32 * (ii & 3) + bb;
    const bool ha = (jj == bb);
    float loc = 0.0f;
#pragma unroll
    for (int q = 0; q < 2; ++q) {
      const int d = (base & 63) + q;
      float v = 0.0f;
      if (he) v = emb[jj * 8192 + ii * 64 + d];
      if (ha) v += __ldcg(&g_accout[ii * 64 + d]);
      out[base + q] = v;
      loc += fabsf(emb[base + q] - v);
    }
    loc = wred(loc);
    if (lane == 0) sRed[w] = loc;
    __syncthreads();
    if (tid == 0) {
      float bp = ((sRed[0] + sRed[1]) + (sRed[2] + sRed[3])) +
                 ((sRed[4] + sRed[5]) + (sRed[6] + sRed[7]));
      __stcg(&g_abspart[p], bp);
      __threadfence();
      arrive_poll(13, 0ull);
    }
    __syncthreads();
  }

  // block 0: parallel final reduction
  if (p == 0) {
    __threadfence();
    sRed[tid] = __ldcg(&g_abspart[tid]) + __ldcg(&g_abspart[tid + 256]);
    __syncthreads();
    for (int off = 128; off; off >>= 1) {
      if (tid < off) sRed[tid] += sRed[tid + off];
      __syncthreads();
    }
    float sl = 0.0f;
    if (tid < 32) sl = wred(__ldcg(&g_err32[tid]));
    if (tid == 0) {
      out[NELEMS] = sl;                                // step_loss
      out[NELEMS + 1] = sRed[0] * (1.0f / 262144.0f);  // sequence_loss
    }
  }
}

// ---------------- launch ----------------
extern "C" void kernel_launch(void* const* d_in, const int* in_sizes, int n_in,
                              void* d_out, int out_size) {
  const float* emb = (const float*)d_in[0];
  const float* W1  = (const float*)d_in[1];
  const float* b1  = (const float*)d_in[2];
  const float* W2  = (const float*)d_in[3];
  const float* b2  = (const float*)d_in[4];
  float* out = (float*)d_out;

  Keys K;
  for (int i = 0; i < NSTEPS; ++i)
    tf2x32(0u, 42u, 0u, (unsigned)i, &K.k0[i], &K.k1[i]);

  kFused<<<NB, NT>>>(emb, W1, b1, W2, b2, out, K);
}